// round 5
// baseline (speedup 1.0000x reference)
#include <cuda_runtime.h>
#include <cuda_fp16.h>
#include <cstdint>
#include <math.h>

#define HD 512
#define BB 128
#define SSQ 2048
#define MT 64         // s-rows per block
#define NT 512        // n-cols per block (full HD)
#define KC 32
#define NCH (HD / KC) // 16
#define ROWB 80       // padded smem row bytes (40 fp16, 64 valid)
#define GT 512        // gemm threads

// smem: two buffers { A[64][80] @0, B[512][80] @5120 }, then partials, cv
#define OF_B 5120
#define BUFSZ 46080
#define OF_PART (2 * BUFSZ)          // 92160, float[8][64] = 2KB
#define OF_CV (OF_PART + 2048)       // 94208, float2[512] = 4KB
#define SMEM_TOTAL (OF_CV + 4096)    // 98304

// ---------------- device scratch ----------------
__device__ float g_WaT[HD * HD];
__device__ float g_c[BB * HD];
__device__ float g_scores[BB * SSQ];
__device__ float g_cpart[4][BB * HD];
__device__ __align__(16) __half g_K16[(size_t)BB * SSQ * HD];  // keys in fp16
__device__ __align__(16) __half g_UaP[(size_t)NCH * HD * 40];  // [kc][n][40]

// ---------------- helpers ----------------
__device__ __forceinline__ uint32_t smem_u32(const void* p) {
    uint32_t a;
    asm("{ .reg .u64 t; cvta.to.shared.u64 t, %1; cvt.u32.u64 %0, t; }" : "=r"(a) : "l"(p));
    return a;
}
__device__ __forceinline__ void cpasync16(uint32_t dst, const void* src) {
    asm volatile("cp.async.cg.shared.global [%0], [%1], 16;" :: "r"(dst), "l"(src));
}
__device__ __forceinline__ void cpasync_commit() {
    asm volatile("cp.async.commit_group;" ::: "memory");
}
__device__ __forceinline__ void cpasync_waitall() {
    asm volatile("cp.async.wait_group 0;" ::: "memory");
}
__device__ __forceinline__ void ldsm4(uint32_t (&r)[4], uint32_t addr) {
    asm volatile("ldmatrix.sync.aligned.m8n8.x4.shared.b16 {%0,%1,%2,%3}, [%4];"
                 : "=r"(r[0]), "=r"(r[1]), "=r"(r[2]), "=r"(r[3]) : "r"(addr));
}
__device__ __forceinline__ void mma16816(float (&d)[4], const uint32_t (&a)[4],
                                         uint32_t b0, uint32_t b1) {
    asm volatile(
        "mma.sync.aligned.m16n8k16.row.col.f32.f16.f16.f32 "
        "{%0,%1,%2,%3}, {%4,%5,%6,%7}, {%8,%9}, {%0,%1,%2,%3};"
        : "+f"(d[0]), "+f"(d[1]), "+f"(d[2]), "+f"(d[3])
        : "r"(a[0]), "r"(a[1]), "r"(a[2]), "r"(a[3]), "r"(b0), "r"(b1));
}

// ---------------- prep kernels ----------------
__global__ void transpose512(const float* __restrict__ in) {
    __shared__ float tile[32][33];
    int bx = blockIdx.x * 32, by = blockIdx.y * 32;
    int tx = threadIdx.x, ty = threadIdx.y;  // (32,8)
#pragma unroll
    for (int i = 0; i < 32; i += 8)
        tile[ty + i][tx] = in[(size_t)(by + ty + i) * HD + bx + tx];
    __syncthreads();
#pragma unroll
    for (int i = 0; i < 32; i += 8)
        g_WaT[(size_t)(bx + ty + i) * HD + by + tx] = tile[tx][ty + i];
}

__global__ void ua_prep(const float* __restrict__ Ua) {
    int n = blockIdx.x;   // 512
    int k = threadIdx.x;  // 512
    float u = Ua[(size_t)n * HD + k];
    g_UaP[((size_t)(k >> 5) * HD + n) * 40 + (k & 31)] = __float2half_rn(u);
}

// keys fp32 -> fp16, streaming, 8 elems/thread
__global__ void keys16_prep(const float* __restrict__ keys) {
    size_t i = ((size_t)blockIdx.x * 512 + threadIdx.x) * 8;
    float4 a = *(const float4*)(keys + i);
    float4 b = *(const float4*)(keys + i + 4);
    __half h[8];
    h[0] = __float2half_rn(a.x); h[1] = __float2half_rn(a.y);
    h[2] = __float2half_rn(a.z); h[3] = __float2half_rn(a.w);
    h[4] = __float2half_rn(b.x); h[5] = __float2half_rn(b.y);
    h[6] = __float2half_rn(b.z); h[7] = __float2half_rn(b.w);
    *(uint4*)(g_K16 + i) = *(const uint4*)h;
}

__global__ void c_kernel(const float* __restrict__ query, const float* __restrict__ ba,
                         const float* __restrict__ bu) {
    int b = blockIdx.x;
    int o = threadIdx.x;  // 512
    __shared__ float q[HD];
    q[o] = query[(size_t)b * HD + o];
    __syncthreads();
    float acc = ba[o] + bu[o];
#pragma unroll 8
    for (int h = 0; h < HD; h++) acc += q[h] * g_WaT[(size_t)h * HD + o];
    g_c[(size_t)b * HD + o] = acc;
}

// ---------------- GEMM tile loads (pure cp.async) ----------------
__device__ __forceinline__ void loadA(uint32_t dstA, const unsigned char* srcA, int tid) {
    if (tid < 256) {
        int r = tid >> 2, c = (tid & 3) * 16;
        cpasync16(dstA + r * ROWB + c, srcA + (size_t)r * (HD * 2) + c);
    }
}
__device__ __forceinline__ void loadB(uint32_t dstB, const __half* __restrict__ src, int tid) {
    const unsigned char* s = (const unsigned char*)src;
#pragma unroll
    for (int i = tid; i < NT * 5; i += GT)
        cpasync16(dstB + i * 16, s + i * 16);
}

__global__ void __launch_bounds__(GT, 1)
gemm_scores_kernel(const float* __restrict__ Va) {
    extern __shared__ unsigned char smem[];
    uint32_t sb = smem_u32(smem);
    int tid = threadIdx.x, lid = tid & 31, wid = tid >> 5;
    int s0 = blockIdx.x * MT, b = blockIdx.y;
    const unsigned char* keysB = (const unsigned char*)(g_K16 + ((size_t)b * SSQ + s0) * HD);
    int wm = wid & 1, wn = wid >> 1;  // warp tile: rows wm*32(+32), cols wn*64(+64)

    // stage {c, Va}
    {
        float2* cv = (float2*)(smem + OF_CV);
        cv[tid] = make_float2(g_c[(size_t)b * HD + tid], Va[tid]);
    }

    // prologue: chunk 0
    loadB(sb + OF_B, g_UaP, tid);
    loadA(sb, keysB, tid);
    cpasync_commit();
    cpasync_waitall();
    __syncthreads();

    float acc[2][8][4];
#pragma unroll
    for (int i = 0; i < 2; i++)
#pragma unroll
        for (int j = 0; j < 8; j++)
#pragma unroll
            for (int c = 0; c < 4; c++) acc[i][j][c] = 0.f;

    uint32_t aoff = (lid & 15) * ROWB + (lid >> 4) * 16;

    for (int kc = 0; kc < NCH; kc++) {
        uint32_t curs = sb + (uint32_t)(kc & 1) * BUFSZ;
        if (kc + 1 < NCH) {
            uint32_t nxt = sb + (uint32_t)((kc + 1) & 1) * BUFSZ;
            loadB(nxt + OF_B, g_UaP + (size_t)(kc + 1) * HD * 40, tid);
            loadA(nxt, keysB + (kc + 1) * 64, tid);
            cpasync_commit();
        }
#pragma unroll
        for (int ks = 0; ks < 2; ks++) {
            uint32_t kb = ks * 32;
            uint32_t ah[2][4], bb[4][4];
#pragma unroll
            for (int i = 0; i < 2; i++)
                ldsm4(ah[i], curs + (wm * 32 + i * 16) * ROWB + aoff + kb);
#pragma unroll
            for (int j2 = 0; j2 < 4; j2++)
                ldsm4(bb[j2], curs + OF_B + (wn * 64 + j2 * 16) * ROWB + aoff + kb);
#pragma unroll
            for (int i = 0; i < 2; i++)
#pragma unroll
                for (int j2 = 0; j2 < 4; j2++) {
                    mma16816(acc[i][2 * j2], ah[i], bb[j2][0], bb[j2][2]);
                    mma16816(acc[i][2 * j2 + 1], ah[i], bb[j2][1], bb[j2][3]);
                }
        }
        if (kc + 1 < NCH) {
            cpasync_waitall();
            __syncthreads();
        }
    }

    // epilogue: part[wn][row] = sum_{o in warp cols} Va[o]*tanh(D[row][o]+c[o])
    float* part = (float*)(smem + OF_PART);
    const float2* cv = (const float2*)(smem + OF_CV);
#pragma unroll
    for (int i = 0; i < 2; i++) {
        float sA = 0.f, sB = 0.f;
#pragma unroll
        for (int j = 0; j < 8; j++) {
            int ol = wn * 64 + j * 8 + (lid & 3) * 2;
            float2 c0 = cv[ol], c1 = cv[ol + 1];
            sA += c0.y * tanhf(acc[i][j][0] + c0.x);
            sA += c1.y * tanhf(acc[i][j][1] + c1.x);
            sB += c0.y * tanhf(acc[i][j][2] + c0.x);
            sB += c1.y * tanhf(acc[i][j][3] + c1.x);
        }
        sA += __shfl_xor_sync(0xffffffffu, sA, 1);
        sA += __shfl_xor_sync(0xffffffffu, sA, 2);
        sB += __shfl_xor_sync(0xffffffffu, sB, 1);
        sB += __shfl_xor_sync(0xffffffffu, sB, 2);
        if ((lid & 3) == 0) {
            int row = wm * 32 + i * 16 + (lid >> 2);
            part[wn * 64 + row] = sA;
            part[wn * 64 + row + 8] = sB;
        }
    }
    __syncthreads();
    if (tid < MT) {
        float v = 0.f;
#pragma unroll
        for (int p = 0; p < 8; p++) v += part[p * 64 + tid];
        g_scores[(size_t)b * SSQ + s0 + tid] = v;
    }
}

// ---------------- softmax over S per batch ----------------
__global__ void softmax_kernel(float* __restrict__ wout) {
    int b = blockIdx.x, t = threadIdx.x;  // 256 threads
    __shared__ float sred[64];
    size_t base = (size_t)b * SSQ;
    float v[SSQ / 256];
    float m = -1e30f;
#pragma unroll
    for (int i = 0; i < SSQ / 256; i++) {
        v[i] = g_scores[base + t + 256 * i];
        m = fmaxf(m, v[i]);
    }
#pragma unroll
    for (int off = 16; off; off >>= 1) m = fmaxf(m, __shfl_xor_sync(0xffffffffu, m, off));
    if ((t & 31) == 0) sred[t >> 5] = m;
    __syncthreads();
    float M = sred[0];
#pragma unroll
    for (int j = 1; j < 8; j++) M = fmaxf(M, sred[j]);
    float sum = 0.f;
#pragma unroll
    for (int i = 0; i < SSQ / 256; i++) {
        float e = __expf(v[i] - M);
        v[i] = e;
        sum += e;
    }
#pragma unroll
    for (int off = 16; off; off >>= 1) sum += __shfl_xor_sync(0xffffffffu, sum, off);
    if ((t & 31) == 0) sred[32 + (t >> 5)] = sum;
    __syncthreads();
    float T = 0.f;
#pragma unroll
    for (int j = 0; j < 8; j++) T += sred[32 + j];
    float inv = 1.f / T;
#pragma unroll
    for (int i = 0; i < SSQ / 256; i++) {
        float wgt = v[i] * inv;
        g_scores[base + t + 256 * i] = wgt;
        if (wout) wout[base + t + 256 * i] = wgt;
    }
}

// ---------------- context from fp16 keys, split 4-way over s ----------------
__global__ void context_part_kernel() {
    int b = blockIdx.x, q = blockIdx.y;
    int t = threadIdx.x;  // 256, each owns half2 column pair
    __shared__ float w[SSQ / 4];
    for (int i = t; i < SSQ / 4; i += 256) w[i] = g_scores[(size_t)b * SSQ + q * (SSQ / 4) + i];
    __syncthreads();
    const __half2* kb = (const __half2*)(g_K16 + ((size_t)b * SSQ + q * (SSQ / 4)) * HD) + t;
    float ax = 0.f, ay = 0.f;
#pragma unroll 8
    for (int s = 0; s < SSQ / 4; s++) {
        float2 f = __half22float2(kb[(size_t)s * (HD / 2)]);
        float ws = w[s];
        ax += ws * f.x;
        ay += ws * f.y;
    }
    g_cpart[q][(size_t)b * HD + 2 * t] = ax;
    g_cpart[q][(size_t)b * HD + 2 * t + 1] = ay;
}
__global__ void context_combine_kernel(float* __restrict__ ctx) {
    int b = blockIdx.x, h = threadIdx.x;
    size_t i = (size_t)b * HD + h;
    ctx[i] = g_cpart[0][i] + g_cpart[1][i] + g_cpart[2][i] + g_cpart[3][i];
}

extern "C" void kernel_launch(void* const* d_in, const int* in_sizes, int n_in,
                              void* d_out, int out_size) {
    const float* query = (const float*)d_in[0];
    const float* keys  = (const float*)d_in[1];
    const float* Wa    = (const float*)d_in[2];
    const float* ba    = (const float*)d_in[3];
    const float* Ua    = (const float*)d_in[4];
    const float* bu    = (const float*)d_in[5];
    const float* Va    = (const float*)d_in[6];
    float* out = (float*)d_out;

    float* ctx_out = out;
    float* w_out = out + BB * HD;
    if (out_size == BB * SSQ) { ctx_out = nullptr; w_out = out; }
    else if (out_size == BB * HD) { w_out = nullptr; }

    static int smem_set = 0;
    if (!smem_set) {
        cudaFuncSetAttribute(gemm_scores_kernel,
                             cudaFuncAttributeMaxDynamicSharedMemorySize, SMEM_TOTAL);
        smem_set = 1;
    }

    keys16_prep<<<(BB * SSQ * HD) / (512 * 8), 512>>>(keys);
    transpose512<<<dim3(16, 16), dim3(32, 8)>>>(Wa);
    ua_prep<<<HD, HD>>>(Ua);
    c_kernel<<<BB, HD>>>(query, ba, bu);
    gemm_scores_kernel<<<dim3(SSQ / MT, BB), GT, SMEM_TOTAL>>>(Va);
    softmax_kernel<<<BB, 256>>>(w_out);
    context_part_kernel<<<dim3(BB, 4), 256>>>();
    if (ctx_out) context_combine_kernel<<<BB, HD>>>(ctx_out);
}